// round 10
// baseline (speedup 1.0000x reference)
#include <cuda_runtime.h>
#include <cuda_bf16.h>
#include <math.h>
#include <stdint.h>

#define DIMV   1024
#define DEPTH  4
#define HEADS  16
#define DHEAD  64
#define INNER  1024
#define MLPV   4096
#define BATCH  2
#define SEQ    1024
#define ROWS   (BATCH*SEQ)

// ---------------- scratch (no allocations allowed; __device__ globals) -------
__device__ float g_qkv[ROWS * 3 * INNER];            // qkv projection (fp32, 24MB)
__device__ float g_x  [ROWS * DIMV];                 // residual stream (8MB)
__device__ __nv_bfloat16 g_ah[ROWS * DIMV];          // activation split hi
__device__ __nv_bfloat16 g_al[ROWS * DIMV];          // activation split lo
__device__ __nv_bfloat16 g_fh[ROWS * MLPV];          // ff hidden split hi
__device__ __nv_bfloat16 g_fl[ROWS * MLPV];          // ff hidden split lo
// transposed + split weights  [N][K] bf16
__device__ __nv_bfloat16 w_qkv_h[DEPTH * 3*INNER * DIMV];
__device__ __nv_bfloat16 w_qkv_l[DEPTH * 3*INNER * DIMV];
__device__ __nv_bfloat16 w_out_h[DEPTH * DIMV * INNER];
__device__ __nv_bfloat16 w_out_l[DEPTH * DIMV * INNER];
__device__ __nv_bfloat16 w_ff1_h[DEPTH * MLPV * DIMV];
__device__ __nv_bfloat16 w_ff1_l[DEPTH * MLPV * DIMV];
__device__ __nv_bfloat16 w_ff2_h[DEPTH * DIMV * MLPV];
__device__ __nv_bfloat16 w_ff2_l[DEPTH * DIMV * MLPV];

// ---------------- small helpers ---------------------------------------------
__device__ __forceinline__ void bf16_split(float v, unsigned short& h, unsigned short& l)
{
    __nv_bfloat16 hb = __float2bfloat16(v);
    __nv_bfloat16 lb = __float2bfloat16(v - __bfloat162float(hb));
    h = __bfloat16_as_ushort(hb);
    l = __bfloat16_as_ushort(lb);
}

__device__ __forceinline__ float gelu_exact(float x)
{
    return 0.5f * x * (1.0f + erff(x * 0.70710678118654752f));
}

__device__ __forceinline__ uint32_t smem_u32(const void* p)
{
    uint32_t r;
    asm("{ .reg .u64 t; cvta.to.shared.u64 t, %1; cvt.u32.u64 %0, t; }"
        : "=r"(r) : "l"(p));
    return r;
}

// ---------------- mma.sync / ldmatrix / cp.async wrappers (sm_80+ PTX) -------
__device__ __forceinline__ void ldsm4(uint32_t* r, uint32_t addr)
{
    asm volatile("ldmatrix.sync.aligned.m8n8.x4.shared.b16 {%0,%1,%2,%3}, [%4];"
        : "=r"(r[0]), "=r"(r[1]), "=r"(r[2]), "=r"(r[3]) : "r"(addr));
}

__device__ __forceinline__ void mma16816(float* d, const uint32_t* a, const uint32_t* b)
{
    asm volatile(
        "mma.sync.aligned.m16n8k16.row.col.f32.bf16.bf16.f32 "
        "{%0,%1,%2,%3}, {%4,%5,%6,%7}, {%8,%9}, {%0,%1,%2,%3};"
        : "+f"(d[0]), "+f"(d[1]), "+f"(d[2]), "+f"(d[3])
        : "r"(a[0]), "r"(a[1]), "r"(a[2]), "r"(a[3]), "r"(b[0]), "r"(b[1]));
}

#define CP_ASYNC16(dst, src) \
    asm volatile("cp.async.cg.shared.global [%0], [%1], 16;" :: "r"(dst), "l"(src))
#define CP_COMMIT() asm volatile("cp.async.commit_group;" ::: "memory")
#define CP_WAIT1()  asm volatile("cp.async.wait_group 1;" ::: "memory")
#define CP_WAIT0()  asm volatile("cp.async.wait_group 0;" ::: "memory")

// ---------------- LayerNorm -> bf16 split ------------------------------------
__global__ void ln_kernel(const float* __restrict__ x,
                          const float* __restrict__ g,
                          const float* __restrict__ b,
                          unsigned short* __restrict__ oh,
                          unsigned short* __restrict__ ol)
{
    __shared__ float red[8];
    __shared__ float sh_mu, sh_rs;
    const int row = blockIdx.x;
    const int tid = threadIdx.x;          // 256 threads, 4 elems each
    float4 v = ((const float4*)(x + (size_t)row * DIMV))[tid];

    float s = (v.x + v.y) + (v.z + v.w);
    #pragma unroll
    for (int o = 16; o; o >>= 1) s += __shfl_xor_sync(0xffffffffu, s, o);
    if ((tid & 31) == 0) red[tid >> 5] = s;
    __syncthreads();
    if (tid == 0) {
        float t = red[0];
        #pragma unroll
        for (int i = 1; i < 8; i++) t += red[i];
        sh_mu = t * (1.0f / DIMV);
    }
    __syncthreads();
    const float mu = sh_mu;
    float d0 = v.x - mu, d1 = v.y - mu, d2 = v.z - mu, d3 = v.w - mu;
    s = d0*d0 + d1*d1 + d2*d2 + d3*d3;
    #pragma unroll
    for (int o = 16; o; o >>= 1) s += __shfl_xor_sync(0xffffffffu, s, o);
    if ((tid & 31) == 0) red[tid >> 5] = s;
    __syncthreads();
    if (tid == 0) {
        float t = red[0];
        #pragma unroll
        for (int i = 1; i < 8; i++) t += red[i];
        sh_rs = rsqrtf(t * (1.0f / DIMV) + 1e-5f);
    }
    __syncthreads();
    const float rs = sh_rs;
    float4 gg = ((const float4*)g)[tid];
    float4 bb = ((const float4*)b)[tid];
    float r0 = d0 * rs * gg.x + bb.x;
    float r1 = d1 * rs * gg.y + bb.y;
    float r2 = d2 * rs * gg.z + bb.z;
    float r3 = d3 * rs * gg.w + bb.w;
    unsigned short h0,h1,h2,h3,l0,l1,l2,l3;
    bf16_split(r0,h0,l0); bf16_split(r1,h1,l1);
    bf16_split(r2,h2,l2); bf16_split(r3,h3,l3);
    uint2 H, L;
    H.x = (uint32_t)h0 | ((uint32_t)h1 << 16);
    H.y = (uint32_t)h2 | ((uint32_t)h3 << 16);
    L.x = (uint32_t)l0 | ((uint32_t)l1 << 16);
    L.y = (uint32_t)l2 | ((uint32_t)l3 << 16);
    ((uint2*)(oh + (size_t)row * DIMV))[tid] = H;
    ((uint2*)(ol + (size_t)row * DIMV))[tid] = L;
}

// ---------------- weight transpose + bf16 split ------------------------------
// W [K][N] fp32 row-major -> Wh/Wl [N][K] bf16
__global__ void wconv_kernel(const float* __restrict__ W,
                             __nv_bfloat16* __restrict__ Wh,
                             __nv_bfloat16* __restrict__ Wl, int K, int N)
{
    __shared__ float t[32][33];
    const int tx = threadIdx.x, ty = threadIdx.y;   // block (32, 8)
    const int k0 = blockIdx.y * 32, n0 = blockIdx.x * 32;
    #pragma unroll
    for (int j = 0; j < 4; j++)
        t[ty + j*8][tx] = W[(size_t)(k0 + ty + j*8) * N + n0 + tx];
    __syncthreads();
    #pragma unroll
    for (int j = 0; j < 4; j++) {
        float v = t[tx][ty + j*8];
        __nv_bfloat16 hb = __float2bfloat16(v);
        __nv_bfloat16 lb = __float2bfloat16(v - __bfloat162float(hb));
        size_t o = (size_t)(n0 + ty + j*8) * K + k0 + tx;
        Wh[o] = hb; Wl[o] = lb;
    }
}

// ---------------- mma.sync GEMM (TN=128): proven R9 kernel -------------------
// 3-term bf16 split: Ah*Bh + Ah*Bl + Al*Bh.
// CTA tile 128x128, 8 warps (warp tile 64x32), K-chunk 32, cp.async 2 stages.
// EPI: 0 = plain fp32, 1 = +bias +residual fp32, 2 = +bias +GELU -> bf16 hi/lo
#define PITCH    40                    // bf16 elems per smem row (80B, LDSM conflict-free)
#define TILE_B   (128 * PITCH * 2)     // 10240 B per tile
#define STAGE_B  (4 * TILE_B)          // Ah, Al, Bh, Bl
#define GSMEM_B  (2 * STAGE_B)         // 81920 B

template <int EPI>
__global__ void __launch_bounds__(256, 1)
mma_gemm(const __nv_bfloat16* __restrict__ Ah, const __nv_bfloat16* __restrict__ Al,
         const __nv_bfloat16* __restrict__ Bh, const __nv_bfloat16* __restrict__ Bl,
         float* __restrict__ C, const float* __restrict__ bias,
         const float* __restrict__ res,
         unsigned short* __restrict__ Ch, unsigned short* __restrict__ Cl,
         int N, int K)
{
    extern __shared__ __align__(128) char smem[];
    const uint32_t sb = smem_u32(smem);
    const int tid  = threadIdx.x;
    const int wid  = tid >> 5, lane = tid & 31;
    const int brow = blockIdx.y * 128, bcol = blockIdx.x * 128;

    const int prow = tid >> 1;
    const int pp   = (tid & 1) * 2;
    const size_t kstride = (size_t)K * 2;

    const char* ga[4];
    ga[0] = (const char*)Ah + (size_t)(brow + prow) * kstride + pp * 16;
    ga[1] = (const char*)Al + (size_t)(brow + prow) * kstride + pp * 16;
    ga[2] = (const char*)Bh + (size_t)(bcol + prow) * kstride + pp * 16;
    ga[3] = (const char*)Bl + (size_t)(bcol + prow) * kstride + pp * 16;
    const uint32_t sdst = sb + (uint32_t)prow * (PITCH * 2) + (uint32_t)pp * 16;

    auto load_chunk = [&](int s, int c) {
        const size_t ko = (size_t)c * 64;
        const uint32_t stg = sdst + s * STAGE_B;
        #pragma unroll
        for (int t = 0; t < 4; t++) {
            const char* g = ga[t] + ko;
            CP_ASYNC16(stg + t * TILE_B,      g);
            CP_ASYNC16(stg + t * TILE_B + 16, g + 16);
        }
    };

    const int m0w = (wid & 1) * 64;
    const int n0w = (wid >> 1) * 32;
    const int lr  = lane & 15;
    const int lc  = (lane >> 4) * 16;

    float acc[4][4][4];
    #pragma unroll
    for (int i = 0; i < 4; i++)
        #pragma unroll
        for (int j = 0; j < 4; j++)
            #pragma unroll
            for (int q = 0; q < 4; q++) acc[i][j][q] = 0.0f;

    const int NC = K >> 5;
    load_chunk(0, 0);
    CP_COMMIT();

    for (int c = 0; c < NC; c++) {
        const int s = c & 1;
        if (c + 1 < NC) { load_chunk(s ^ 1, c + 1); CP_COMMIT(); CP_WAIT1(); }
        else            { CP_WAIT0(); }
        __syncthreads();

        const uint32_t stg = sb + s * STAGE_B;
        const uint32_t sAh = stg;
        const uint32_t sAl = stg + TILE_B;
        const uint32_t sBh = stg + 2 * TILE_B;
        const uint32_t sBl = stg + 3 * TILE_B;

        #pragma unroll
        for (int kb = 0; kb < 2; kb++) {
            const uint32_t kofs = kb * 32 + lc;
            uint32_t ah[4][4], al[4][4], bh[4][2], bl[4][2];
            #pragma unroll
            for (int mi = 0; mi < 4; mi++) {
                const uint32_t ro = (uint32_t)(m0w + mi * 16 + lr) * (PITCH * 2) + kofs;
                ldsm4(ah[mi], sAh + ro);
                ldsm4(al[mi], sAl + ro);
            }
            #pragma unroll
            for (int g2 = 0; g2 < 2; g2++) {
                const uint32_t ro = (uint32_t)(n0w + g2 * 16 + lr) * (PITCH * 2) + kofs;
                uint32_t rh[4], rl[4];
                ldsm4(rh, sBh + ro);
                ldsm4(rl, sBl + ro);
                bh[2*g2][0] = rh[0]; bh[2*g2][1] = rh[2];
                bh[2*g2+1][0] = rh[1]; bh[2*g2+1][1] = rh[3];
                bl[2*g2][0] = rl[0]; bl[2*g2][1] = rl[2];
                bl[2*g2+1][0] = rl[1]; bl[2*g2+1][1] = rl[3];
            }
            #pragma unroll
            for (int mi = 0; mi < 4; mi++)
                #pragma unroll
                for (int ni = 0; ni < 4; ni++) {
                    mma16816(acc[mi][ni], ah[mi], bh[ni]);
                    mma16816(acc[mi][ni], ah[mi], bl[ni]);
                    mma16816(acc[mi][ni], al[mi], bh[ni]);
                }
        }
        __syncthreads();
    }

    const int tr  = lane >> 2;
    const int tc2 = (lane & 3) * 2;
    #pragma unroll
    for (int mi = 0; mi < 4; mi++) {
        #pragma unroll
        for (int ni = 0; ni < 4; ni++) {
            const int col = bcol + n0w + ni * 8 + tc2;
            #pragma unroll
            for (int hf = 0; hf < 2; hf++) {
                const int row = brow + m0w + mi * 16 + tr + hf * 8;
                float v0 = acc[mi][ni][hf * 2];
                float v1 = acc[mi][ni][hf * 2 + 1];
                if (EPI == 0) {
                    *(float2*)(C + (size_t)row * N + col) = make_float2(v0, v1);
                } else if (EPI == 1) {
                    const float2 bb = *(const float2*)(bias + col);
                    const float2 rr = *(const float2*)(res + (size_t)row * N + col);
                    *(float2*)(C + (size_t)row * N + col) =
                        make_float2(v0 + bb.x + rr.x, v1 + bb.y + rr.y);
                } else {
                    const float2 bb = *(const float2*)(bias + col);
                    float g0 = gelu_exact(v0 + bb.x);
                    float g1 = gelu_exact(v1 + bb.y);
                    unsigned short h0, l0, h1, l1;
                    bf16_split(g0, h0, l0);
                    bf16_split(g1, h1, l1);
                    *(uint32_t*)(Ch + (size_t)row * N + col) =
                        (uint32_t)h0 | ((uint32_t)h1 << 16);
                    *(uint32_t*)(Cl + (size_t)row * N + col) =
                        (uint32_t)l0 | ((uint32_t)l1 << 16);
                }
            }
        }
    }
}

// ---------------- mma.sync GEMM (TN=256): 128x256 CTA, 64x64 warp tiles ------
// Higher smem-reuse variant: LDSM traffic per MMA halves -> tensor-bound.
// EPI: 0 = plain fp32, 2 = +bias +GELU -> bf16 hi/lo
#define A_TILE256 (128 * PITCH * 2)                    // 10240 B
#define B_TILE256 (256 * PITCH * 2)                    // 20480 B
#define STAGE256  (2 * A_TILE256 + 2 * B_TILE256)      // 61440 B
#define GSMEM256  (2 * STAGE256)                       // 122880 B
#define AOFF_L    A_TILE256
#define BOFF_H    (2 * A_TILE256)
#define BOFF_L    (2 * A_TILE256 + B_TILE256)

template <int EPI>
__global__ void __launch_bounds__(256, 1)
mma_gemm256(const __nv_bfloat16* __restrict__ Ah, const __nv_bfloat16* __restrict__ Al,
            const __nv_bfloat16* __restrict__ Bh, const __nv_bfloat16* __restrict__ Bl,
            float* __restrict__ C, const float* __restrict__ bias,
            unsigned short* __restrict__ Ch, unsigned short* __restrict__ Cl,
            int N, int K)
{
    extern __shared__ __align__(128) char smem[];
    const uint32_t sb = smem_u32(smem);
    const int tid  = threadIdx.x;
    const int wid  = tid >> 5, lane = tid & 31;
    const int brow = blockIdx.y * 128, bcol = blockIdx.x * 256;

    // producer mapping: A -> row tid/2, 2x16B; B -> row tid, 4x16B (hi & lo)
    const int prow = tid >> 1;
    const int pp   = (tid & 1) * 2;
    const size_t kstride = (size_t)K * 2;

    const char* gAh = (const char*)Ah + (size_t)(brow + prow) * kstride + pp * 16;
    const char* gAl = (const char*)Al + (size_t)(brow + prow) * kstride + pp * 16;
    const char* gBh = (const char*)Bh + (size_t)(bcol + tid) * kstride;
    const char* gBl = (const char*)Bl + (size_t)(bcol + tid) * kstride;

    const uint32_t sA = sb + (uint32_t)prow * (PITCH * 2) + (uint32_t)pp * 16;
    const uint32_t sB = sb + (uint32_t)tid * (PITCH * 2);

    auto load_chunk = [&](int s, int c) {
        const size_t ko = (size_t)c * 64;
        const uint32_t so = s * STAGE256;
        CP_ASYNC16(sA + so,               gAh + ko);
        CP_ASYNC16(sA + so + 16,          gAh + ko + 16);
        CP_ASYNC16(sA + so + AOFF_L,      gAl + ko);
        CP_ASYNC16(sA + so + AOFF_L + 16, gAl + ko + 16);
        #pragma unroll
        for (int j = 0; j < 4; j++) {
            CP_ASYNC16(sB + so + BOFF_H + j * 16, gBh + ko + j * 16);
            CP_ASYNC16(sB + so + BOFF_L + j * 16, gBl + ko + j * 16);
        }
    };

    // consumer mapping: 2(m) x 4(n) warps, warp tile 64x64
    const int m0w = (wid & 1) * 64;
    const int n0w = (wid >> 1) * 64;
    const int lr  = lane & 15;
    const int lc  = (lane >> 4) * 16;

    float acc[4][8][4];
    #pragma unroll
    for (int i = 0; i < 4; i++)
        #pragma unroll
        for (int j = 0; j < 8; j++)
            #pragma unroll
            for (int q = 0; q < 4; q++) acc[i][j][q] = 0.0f;

    const int NC = K >> 5;
    load_chunk(0, 0);
    CP_COMMIT();

    for (int c = 0; c < NC; c++) {
        const int s = c & 1;
        if (c + 1 < NC) { load_chunk(s ^ 1, c + 1); CP_COMMIT(); CP_WAIT1(); }
        else            { CP_WAIT0(); }
        __syncthreads();

        const uint32_t stg = sb + s * STAGE256;
        const uint32_t sAhp = stg;
        const uint32_t sAlp = stg + AOFF_L;
        const uint32_t sBhp = stg + BOFF_H;
        const uint32_t sBlp = stg + BOFF_L;

        #pragma unroll
        for (int kb = 0; kb < 2; kb++) {
            const uint32_t kofs = kb * 32 + lc;
            uint32_t ah[4][4], al[4][4];
            #pragma unroll
            for (int mi = 0; mi < 4; mi++) {
                const uint32_t ro = (uint32_t)(m0w + mi * 16 + lr) * (PITCH * 2) + kofs;
                ldsm4(ah[mi], sAhp + ro);
                ldsm4(al[mi], sAlp + ro);
            }
            #pragma unroll
            for (int g = 0; g < 4; g++) {      // 16 n-rows per group -> 2 ni
                const uint32_t ro = (uint32_t)(n0w + g * 16 + lr) * (PITCH * 2) + kofs;
                uint32_t rh[4], rl[4];
                ldsm4(rh, sBhp + ro);
                ldsm4(rl, sBlp + ro);
                uint32_t bh2[2][2], bl2[2][2];
                bh2[0][0] = rh[0]; bh2[0][1] = rh[2];
                bh2[1][0] = rh[1]; bh2[1][1] = rh[3];
                bl2[0][0] = rl[0]; bl2[0][1] = rl[2];
                bl2[1][0] = rl[1]; bl2[1][1] = rl[3];
                // term-outer ordering for ILP across independent accumulators
                #pragma unroll
                for (int mi = 0; mi < 4; mi++)
                    #pragma unroll
                    for (int nn = 0; nn < 2; nn++)
                        mma16816(acc[mi][g*2+nn], ah[mi], bh2[nn]);
                #pragma unroll
                for (int mi = 0; mi < 4; mi++)
                    #pragma unroll
                    for (int nn = 0; nn < 2; nn++)
                        mma16816(acc[mi][g*2+nn], ah[mi], bl2[nn]);
                #pragma unroll
                for (int mi = 0; mi < 4; mi++)
                    #pragma unroll
                    for (int nn = 0; nn < 2; nn++)
                        mma16816(acc[mi][g*2+nn], al[mi], bh2[nn]);
            }
        }
        __syncthreads();
    }

    const int tr  = lane >> 2;
    const int tc2 = (lane & 3) * 2;
    #pragma unroll
    for (int mi = 0; mi < 4; mi++) {
        #pragma unroll
        for (int ni = 0; ni < 8; ni++) {
            const int col = bcol + n0w + ni * 8 + tc2;
            #pragma unroll
            for (int hf = 0; hf < 2; hf++) {
                const int row = brow + m0w + mi * 16 + tr + hf * 8;
                float v0 = acc[mi][ni][hf * 2];
                float v1 = acc[mi][ni][hf * 2 + 1];
                if (EPI == 0) {
                    *(float2*)(C + (size_t)row * N + col) = make_float2(v0, v1);
                } else {
                    const float2 bb = *(const float2*)(bias + col);
                    float g0 = gelu_exact(v0 + bb.x);
                    float g1 = gelu_exact(v1 + bb.y);
                    unsigned short h0, l0, h1, l1;
                    bf16_split(g0, h0, l0);
                    bf16_split(g1, h1, l1);
                    *(uint32_t*)(Ch + (size_t)row * N + col) =
                        (uint32_t)h0 | ((uint32_t)h1 << 16);
                    *(uint32_t*)(Cl + (size_t)row * N + col) =
                        (uint32_t)l0 | ((uint32_t)l1 << 16);
                }
            }
        }
    }
}

// ---------------- Flash attention (fp32, online softmax) -> bf16 split -------
__global__ void __launch_bounds__(128)
flash_kernel(const float* __restrict__ qkv, const int* __restrict__ mask,
             unsigned short* __restrict__ oh, unsigned short* __restrict__ ol)
{
    __shared__ __align__(16) float Ks[64][64];
    __shared__ __align__(16) float Vs[64][64];
    __shared__ unsigned char   Ms[128][68];

    const int bh = blockIdx.y;
    const int b  = bh >> 4;
    const int h  = bh & 15;
    const int q0 = blockIdx.x * 128;
    const int tid = threadIdx.x;
    const int qrow = q0 + tid;
    const float scale = 0.125f;

    float q[64];
    const float* qp = qkv + (size_t)(b * SEQ + qrow) * (3 * INNER) + h * DHEAD;
    #pragma unroll
    for (int d = 0; d < 64; d += 4) {
        float4 t = *(const float4*)(qp + d);
        q[d] = t.x * scale; q[d+1] = t.y * scale;
        q[d+2] = t.z * scale; q[d+3] = t.w * scale;
    }

    float o[64];
    #pragma unroll
    for (int d = 0; d < 64; d++) o[d] = 0.0f;
    float m = -INFINITY, l = 0.0f;

    const int* mrow = mask + ((size_t)b * SEQ + qrow) * SEQ;

    for (int kt = 0; kt < SEQ; kt += 64) {
        {
            const int r = tid >> 1;
            const int c = (tid & 1) * 32;
            const float* kp = qkv + (size_t)(b * SEQ + kt + r) * (3 * INNER)
                              + INNER + h * DHEAD + c;
            const float* vp = kp + INNER;
            #pragma unroll
            for (int j = 0; j < 32; j += 4) {
                *(float4*)&Ks[r][c + j] = *(const float4*)(kp + j);
                *(float4*)&Vs[r][c + j] = *(const float4*)(vp + j);
            }
        }
        {
            const int* mp = mrow + kt;
            #pragma unroll
            for (int j = 0; j < 64; j += 4) {
                int4 mm = *(const int4*)(mp + j);
                Ms[tid][j]     = (unsigned char)mm.x;
                Ms[tid][j + 1] = (unsigned char)mm.y;
                Ms[tid][j + 2] = (unsigned char)mm.z;
                Ms[tid][j + 3] = (unsigned char)mm.w;
            }
        }
        __syncthreads();

        #pragma unroll 1
        for (int kk = 0; kk < 64; kk++) {
            float s0 = 0.f, s1 = 0.f, s2 = 0.f, s3 = 0.f;
            #pragma unroll
            for (int d = 0; d < 64; d += 4) {
                float4 kv = *(const float4*)&Ks[kk][d];
                s0 += q[d]     * kv.x;
                s1 += q[d + 1] * kv.y;
                s2 += q[d + 2] * kv.z;
                s3 += q[d + 3] * kv.w;
            }
            float s = (s0 + s1) + (s2 + s3);
            if (Ms[tid][kk] == 0) s = -1e9f;

            float p;
            if (s > m) {
                float c = __expf(m - s);
                l *= c;
                #pragma unroll
                for (int d = 0; d < 64; d++) o[d] *= c;
                m = s;
                p = 1.0f;
            } else {
                p = __expf(s - m);
            }
            l += p;
            #pragma unroll
            for (int d = 0; d < 64; d += 4) {
                float4 vv = *(const float4*)&Vs[kk][d];
                o[d]     += p * vv.x;
                o[d + 1] += p * vv.y;
                o[d + 2] += p * vv.z;
                o[d + 3] += p * vv.w;
            }
        }
        __syncthreads();
    }

    const float inv = 1.0f / l;
    unsigned short* hp = oh + (size_t)(b * SEQ + qrow) * INNER + h * DHEAD;
    unsigned short* lp = ol + (size_t)(b * SEQ + qrow) * INNER + h * DHEAD;
    #pragma unroll
    for (int d0 = 0; d0 < 64; d0 += 8) {
        uint32_t hw[4], lw[4];
        #pragma unroll
        for (int j = 0; j < 4; j++) {
            float v0 = o[d0 + 2*j]     * inv;
            float v1 = o[d0 + 2*j + 1] * inv;
            unsigned short h0, l0, h1, l1;
            bf16_split(v0, h0, l0);
            bf16_split(v1, h1, l1);
            hw[j] = (uint32_t)h0 | ((uint32_t)h1 << 16);
            lw[j] = (uint32_t)l0 | ((uint32_t)l1 << 16);
        }
        *(uint4*)(hp + d0) = make_uint4(hw[0], hw[1], hw[2], hw[3]);
        *(uint4*)(lp + d0) = make_uint4(lw[0], lw[1], lw[2], lw[3]);
    }
}

// ---------------- host orchestration ----------------------------------------
extern "C" void kernel_launch(void* const* d_in, const int* in_sizes, int n_in,
                              void* d_out, int out_size)
{
    (void)in_sizes; (void)n_in; (void)out_size;
    const float* x_in  = (const float*)d_in[0];
    const int*   mask  = (const int*)  d_in[1];
    const float* ln1_g = (const float*)d_in[2];
    const float* ln1_b = (const float*)d_in[3];
    const float* qkv_w = (const float*)d_in[4];
    const float* out_w = (const float*)d_in[5];
    const float* out_b = (const float*)d_in[6];
    const float* ln2_g = (const float*)d_in[7];
    const float* ln2_b = (const float*)d_in[8];
    const float* ff1_w = (const float*)d_in[9];
    const float* ff1_b = (const float*)d_in[10];
    const float* ff2_w = (const float*)d_in[11];
    const float* ff2_b = (const float*)d_in[12];

    cudaFuncSetAttribute(mma_gemm<1>,    cudaFuncAttributeMaxDynamicSharedMemorySize, GSMEM_B);
    cudaFuncSetAttribute(mma_gemm256<0>, cudaFuncAttributeMaxDynamicSharedMemorySize, GSMEM256);
    cudaFuncSetAttribute(mma_gemm256<2>, cudaFuncAttributeMaxDynamicSharedMemorySize, GSMEM256);

    float *p_qkv, *p_x;
    __nv_bfloat16 *p_ah, *p_al, *p_fh, *p_fl;
    __nv_bfloat16 *pwqh, *pwql, *pwoh, *pwol, *pw1h, *pw1l, *pw2h, *pw2l;
    cudaGetSymbolAddress((void**)&p_qkv, g_qkv);
    cudaGetSymbolAddress((void**)&p_x,   g_x);
    cudaGetSymbolAddress((void**)&p_ah,  g_ah);
    cudaGetSymbolAddress((void**)&p_al,  g_al);
    cudaGetSymbolAddress((void**)&p_fh,  g_fh);
    cudaGetSymbolAddress((void**)&p_fl,  g_fl);
    cudaGetSymbolAddress((void**)&pwqh,  w_qkv_h);
    cudaGetSymbolAddress((void**)&pwql,  w_qkv_l);
    cudaGetSymbolAddress((void**)&pwoh,  w_out_h);
    cudaGetSymbolAddress((void**)&pwol,  w_out_l);
    cudaGetSymbolAddress((void**)&pw1h,  w_ff1_h);
    cudaGetSymbolAddress((void**)&pw1l,  w_ff1_l);
    cudaGetSymbolAddress((void**)&pw2h,  w_ff2_h);
    cudaGetSymbolAddress((void**)&pw2l,  w_ff2_l);

    // ---- per-call weight transpose + split ----
    const dim3 cb(32, 8);
    for (int l = 0; l < DEPTH; l++) {
        wconv_kernel<<<dim3(3*INNER/32, DIMV/32), cb>>>(
            qkv_w + (size_t)l * DIMV * 3*INNER,
            pwqh + (size_t)l * 3*INNER * DIMV, pwql + (size_t)l * 3*INNER * DIMV,
            DIMV, 3*INNER);
        wconv_kernel<<<dim3(DIMV/32, INNER/32), cb>>>(
            out_w + (size_t)l * INNER * DIMV,
            pwoh + (size_t)l * DIMV * INNER, pwol + (size_t)l * DIMV * INNER,
            INNER, DIMV);
        wconv_kernel<<<dim3(MLPV/32, DIMV/32), cb>>>(
            ff1_w + (size_t)l * DIMV * MLPV,
            pw1h + (size_t)l * MLPV * DIMV, pw1l + (size_t)l * MLPV * DIMV,
            DIMV, MLPV);
        wconv_kernel<<<dim3(DIMV/32, MLPV/32), cb>>>(
            ff2_w + (size_t)l * MLPV * DIMV,
            pw2h + (size_t)l * DIMV * MLPV, pw2l + (size_t)l * DIMV * MLPV,
            MLPV, DIMV);
    }

    for (int l = 0; l < DEPTH; l++) {
        const float* xsrc = (l == 0) ? x_in : p_x;

        // h = LN1(x) -> bf16 split
        ln_kernel<<<ROWS, 256>>>(xsrc, ln1_g + l * DIMV, ln1_b + l * DIMV,
                                 (unsigned short*)p_ah, (unsigned short*)p_al);

        // qkv = h @ qkv_w[l]  (fp32 out for attention)  [TN=256]
        mma_gemm256<0><<<dim3(3*INNER/256, ROWS/128), 256, GSMEM256>>>(
            p_ah, p_al,
            pwqh + (size_t)l * 3*INNER * DIMV, pwql + (size_t)l * 3*INNER * DIMV,
            p_qkv, nullptr, nullptr, nullptr, 3*INNER, DIMV);

        // o = attention(q,k,v,mask) -> bf16 split
        flash_kernel<<<dim3(SEQ/128, BATCH*HEADS), 128>>>(
            p_qkv, mask, (unsigned short*)p_ah, (unsigned short*)p_al);

        // x = o @ out_w[l] + out_b[l] + x   [TN=128]
        mma_gemm<1><<<dim3(DIMV/128, ROWS/128), 256, GSMEM_B>>>(
            p_ah, p_al,
            pwoh + (size_t)l * DIMV * INNER, pwol + (size_t)l * DIMV * INNER,
            p_x, out_b + l * DIMV, xsrc, nullptr, nullptr, DIMV, INNER);

        // h = LN2(x) -> bf16 split
        ln_kernel<<<ROWS, 256>>>(p_x, ln2_g + l * DIMV, ln2_b + l * DIMV,
                                 (unsigned short*)p_ah, (unsigned short*)p_al);

        // ffh = gelu(h @ ff1_w[l] + ff1_b[l]) -> bf16 split  [TN=256]
        mma_gemm256<2><<<dim3(MLPV/256, ROWS/128), 256, GSMEM256>>>(
            p_ah, p_al,
            pw1h + (size_t)l * MLPV * DIMV, pw1l + (size_t)l * MLPV * DIMV,
            nullptr, ff1_b + l * MLPV,
            (unsigned short*)p_fh, (unsigned short*)p_fl, MLPV, DIMV);

        // x = ffh @ ff2_w[l] + ff2_b[l] + x   (last layer writes d_out) [TN=128]
        float* xdst = (l == DEPTH - 1) ? (float*)d_out : p_x;
        mma_gemm<1><<<dim3(DIMV/128, ROWS/128), 256, GSMEM_B>>>(
            p_fh, p_fl,
            pw2h + (size_t)l * DIMV * MLPV, pw2l + (size_t)l * DIMV * MLPV,
            xdst, ff2_b + l * DIMV, p_x, nullptr, nullptr, DIMV, MLPV);
    }
}

// round 12
// speedup vs baseline: 1.0681x; 1.0681x over previous
#include <cuda_runtime.h>
#include <cuda_bf16.h>
#include <math.h>
#include <stdint.h>

#define DIMV   1024
#define DEPTH  4
#define HEADS  16
#define DHEAD  64
#define INNER  1024
#define MLPV   4096
#define BATCH  2
#define SEQ    1024
#define ROWS   (BATCH*SEQ)

// ---------------- scratch (no allocations allowed; __device__ globals) -------
__device__ float g_qkv[ROWS * 3 * INNER];            // qkv projection (fp32, 24MB)
__device__ float g_x  [ROWS * DIMV];                 // residual stream (8MB)
__device__ __nv_bfloat16 g_ah[ROWS * DIMV];          // activation split hi
__device__ __nv_bfloat16 g_al[ROWS * DIMV];          // activation split lo
__device__ __nv_bfloat16 g_fh[ROWS * MLPV];          // ff hidden split hi
__device__ __nv_bfloat16 g_fl[ROWS * MLPV];          // ff hidden split lo
// transposed + split weights  [N][K] bf16
__device__ __nv_bfloat16 w_qkv_h[DEPTH * 3*INNER * DIMV];
__device__ __nv_bfloat16 w_qkv_l[DEPTH * 3*INNER * DIMV];
__device__ __nv_bfloat16 w_out_h[DEPTH * DIMV * INNER];
__device__ __nv_bfloat16 w_out_l[DEPTH * DIMV * INNER];
__device__ __nv_bfloat16 w_ff1_h[DEPTH * MLPV * DIMV];
__device__ __nv_bfloat16 w_ff1_l[DEPTH * MLPV * DIMV];
__device__ __nv_bfloat16 w_ff2_h[DEPTH * DIMV * MLPV];
__device__ __nv_bfloat16 w_ff2_l[DEPTH * DIMV * MLPV];

// ---------------- small helpers ---------------------------------------------
__device__ __forceinline__ void bf16_split(float v, unsigned short& h, unsigned short& l)
{
    __nv_bfloat16 hb = __float2bfloat16(v);
    __nv_bfloat16 lb = __float2bfloat16(v - __bfloat162float(hb));
    h = __bfloat16_as_ushort(hb);
    l = __bfloat16_as_ushort(lb);
}

__device__ __forceinline__ float gelu_exact(float x)
{
    return 0.5f * x * (1.0f + erff(x * 0.70710678118654752f));
}

__device__ __forceinline__ uint32_t smem_u32(const void* p)
{
    uint32_t r;
    asm("{ .reg .u64 t; cvta.to.shared.u64 t, %1; cvt.u32.u64 %0, t; }"
        : "=r"(r) : "l"(p));
    return r;
}

// ---------------- mma.sync / ldmatrix / cp.async wrappers (sm_80+ PTX) -------
__device__ __forceinline__ void ldsm4(uint32_t* r, uint32_t addr)
{
    asm volatile("ldmatrix.sync.aligned.m8n8.x4.shared.b16 {%0,%1,%2,%3}, [%4];"
        : "=r"(r[0]), "=r"(r[1]), "=r"(r[2]), "=r"(r[3]) : "r"(addr));
}

__device__ __forceinline__ void mma16816(float* d, const uint32_t* a, const uint32_t* b)
{
    asm volatile(
        "mma.sync.aligned.m16n8k16.row.col.f32.bf16.bf16.f32 "
        "{%0,%1,%2,%3}, {%4,%5,%6,%7}, {%8,%9}, {%0,%1,%2,%3};"
        : "+f"(d[0]), "+f"(d[1]), "+f"(d[2]), "+f"(d[3])
        : "r"(a[0]), "r"(a[1]), "r"(a[2]), "r"(a[3]), "r"(b[0]), "r"(b[1]));
}

#define CP_ASYNC16(dst, src) \
    asm volatile("cp.async.cg.shared.global [%0], [%1], 16;" :: "r"(dst), "l"(src))
#define CP_COMMIT() asm volatile("cp.async.commit_group;" ::: "memory")
#define CP_WAIT1()  asm volatile("cp.async.wait_group 1;" ::: "memory")
#define CP_WAIT0()  asm volatile("cp.async.wait_group 0;" ::: "memory")

// ---------------- LayerNorm -> bf16 split ------------------------------------
__global__ void ln_kernel(const float* __restrict__ x,
                          const float* __restrict__ g,
                          const float* __restrict__ b,
                          unsigned short* __restrict__ oh,
                          unsigned short* __restrict__ ol)
{
    __shared__ float red[8];
    __shared__ float sh_mu, sh_rs;
    const int row = blockIdx.x;
    const int tid = threadIdx.x;          // 256 threads, 4 elems each
    float4 v = ((const float4*)(x + (size_t)row * DIMV))[tid];

    float s = (v.x + v.y) + (v.z + v.w);
    #pragma unroll
    for (int o = 16; o; o >>= 1) s += __shfl_xor_sync(0xffffffffu, s, o);
    if ((tid & 31) == 0) red[tid >> 5] = s;
    __syncthreads();
    if (tid == 0) {
        float t = red[0];
        #pragma unroll
        for (int i = 1; i < 8; i++) t += red[i];
        sh_mu = t * (1.0f / DIMV);
    }
    __syncthreads();
    const float mu = sh_mu;
    float d0 = v.x - mu, d1 = v.y - mu, d2 = v.z - mu, d3 = v.w - mu;
    s = d0*d0 + d1*d1 + d2*d2 + d3*d3;
    #pragma unroll
    for (int o = 16; o; o >>= 1) s += __shfl_xor_sync(0xffffffffu, s, o);
    if ((tid & 31) == 0) red[tid >> 5] = s;
    __syncthreads();
    if (tid == 0) {
        float t = red[0];
        #pragma unroll
        for (int i = 1; i < 8; i++) t += red[i];
        sh_rs = rsqrtf(t * (1.0f / DIMV) + 1e-5f);
    }
    __syncthreads();
    const float rs = sh_rs;
    float4 gg = ((const float4*)g)[tid];
    float4 bb = ((const float4*)b)[tid];
    float r0 = d0 * rs * gg.x + bb.x;
    float r1 = d1 * rs * gg.y + bb.y;
    float r2 = d2 * rs * gg.z + bb.z;
    float r3 = d3 * rs * gg.w + bb.w;
    unsigned short h0,h1,h2,h3,l0,l1,l2,l3;
    bf16_split(r0,h0,l0); bf16_split(r1,h1,l1);
    bf16_split(r2,h2,l2); bf16_split(r3,h3,l3);
    uint2 H, L;
    H.x = (uint32_t)h0 | ((uint32_t)h1 << 16);
    H.y = (uint32_t)h2 | ((uint32_t)h3 << 16);
    L.x = (uint32_t)l0 | ((uint32_t)l1 << 16);
    L.y = (uint32_t)l2 | ((uint32_t)l3 << 16);
    ((uint2*)(oh + (size_t)row * DIMV))[tid] = H;
    ((uint2*)(ol + (size_t)row * DIMV))[tid] = L;
}

// ---------------- weight transpose + bf16 split ------------------------------
// W [K][N] fp32 row-major -> Wh/Wl [N][K] bf16
__global__ void wconv_kernel(const float* __restrict__ W,
                             __nv_bfloat16* __restrict__ Wh,
                             __nv_bfloat16* __restrict__ Wl, int K, int N)
{
    __shared__ float t[32][33];
    const int tx = threadIdx.x, ty = threadIdx.y;   // block (32, 8)
    const int k0 = blockIdx.y * 32, n0 = blockIdx.x * 32;
    #pragma unroll
    for (int j = 0; j < 4; j++)
        t[ty + j*8][tx] = W[(size_t)(k0 + ty + j*8) * N + n0 + tx];
    __syncthreads();
    #pragma unroll
    for (int j = 0; j < 4; j++) {
        float v = t[tx][ty + j*8];
        __nv_bfloat16 hb = __float2bfloat16(v);
        __nv_bfloat16 lb = __float2bfloat16(v - __bfloat162float(hb));
        size_t o = (size_t)(n0 + ty + j*8) * K + k0 + tx;
        Wh[o] = hb; Wl[o] = lb;
    }
}

// ---------------- mma.sync GEMM (TN=128): proven R9 kernel, 2 CTAs/SM --------
// 3-term bf16 split: Ah*Bh + Ah*Bl + Al*Bh.
// CTA tile 128x128, 8 warps (warp tile 64x32), K-chunk 32, cp.async 2 stages.
// EPI: 0 = plain fp32, 1 = +bias +residual fp32, 2 = +bias +GELU -> bf16 hi/lo
#define PITCH    40                    // bf16 elems per smem row (80B, LDSM conflict-free)
#define TILE_B   (128 * PITCH * 2)     // 10240 B per tile
#define STAGE_B  (4 * TILE_B)          // Ah, Al, Bh, Bl
#define GSMEM_B  (2 * STAGE_B)         // 81920 B

template <int EPI>
__global__ void __launch_bounds__(256, 2)
mma_gemm(const __nv_bfloat16* __restrict__ Ah, const __nv_bfloat16* __restrict__ Al,
         const __nv_bfloat16* __restrict__ Bh, const __nv_bfloat16* __restrict__ Bl,
         float* __restrict__ C, const float* __restrict__ bias,
         const float* __restrict__ res,
         unsigned short* __restrict__ Ch, unsigned short* __restrict__ Cl,
         int N, int K)
{
    extern __shared__ __align__(128) char smem[];
    const uint32_t sb = smem_u32(smem);
    const int tid  = threadIdx.x;
    const int wid  = tid >> 5, lane = tid & 31;
    const int brow = blockIdx.y * 128, bcol = blockIdx.x * 128;

    const int prow = tid >> 1;
    const int pp   = (tid & 1) * 2;
    const size_t kstride = (size_t)K * 2;

    const char* ga[4];
    ga[0] = (const char*)Ah + (size_t)(brow + prow) * kstride + pp * 16;
    ga[1] = (const char*)Al + (size_t)(brow + prow) * kstride + pp * 16;
    ga[2] = (const char*)Bh + (size_t)(bcol + prow) * kstride + pp * 16;
    ga[3] = (const char*)Bl + (size_t)(bcol + prow) * kstride + pp * 16;
    const uint32_t sdst = sb + (uint32_t)prow * (PITCH * 2) + (uint32_t)pp * 16;

    auto load_chunk = [&](int s, int c) {
        const size_t ko = (size_t)c * 64;
        const uint32_t stg = sdst + s * STAGE_B;
        #pragma unroll
        for (int t = 0; t < 4; t++) {
            const char* g = ga[t] + ko;
            CP_ASYNC16(stg + t * TILE_B,      g);
            CP_ASYNC16(stg + t * TILE_B + 16, g + 16);
        }
    };

    const int m0w = (wid & 1) * 64;
    const int n0w = (wid >> 1) * 32;
    const int lr  = lane & 15;
    const int lc  = (lane >> 4) * 16;

    float acc[4][4][4];
    #pragma unroll
    for (int i = 0; i < 4; i++)
        #pragma unroll
        for (int j = 0; j < 4; j++)
            #pragma unroll
            for (int q = 0; q < 4; q++) acc[i][j][q] = 0.0f;

    const int NC = K >> 5;
    load_chunk(0, 0);
    CP_COMMIT();

    for (int c = 0; c < NC; c++) {
        const int s = c & 1;
        if (c + 1 < NC) { load_chunk(s ^ 1, c + 1); CP_COMMIT(); CP_WAIT1(); }
        else            { CP_WAIT0(); }
        __syncthreads();

        const uint32_t stg = sb + s * STAGE_B;
        const uint32_t sAh = stg;
        const uint32_t sAl = stg + TILE_B;
        const uint32_t sBh = stg + 2 * TILE_B;
        const uint32_t sBl = stg + 3 * TILE_B;

        #pragma unroll
        for (int kb = 0; kb < 2; kb++) {
            const uint32_t kofs = kb * 32 + lc;
            uint32_t ah[4][4], al[4][4], bh[4][2], bl[4][2];
            #pragma unroll
            for (int mi = 0; mi < 4; mi++) {
                const uint32_t ro = (uint32_t)(m0w + mi * 16 + lr) * (PITCH * 2) + kofs;
                ldsm4(ah[mi], sAh + ro);
                ldsm4(al[mi], sAl + ro);
            }
            #pragma unroll
            for (int g2 = 0; g2 < 2; g2++) {
                const uint32_t ro = (uint32_t)(n0w + g2 * 16 + lr) * (PITCH * 2) + kofs;
                uint32_t rh[4], rl[4];
                ldsm4(rh, sBh + ro);
                ldsm4(rl, sBl + ro);
                bh[2*g2][0] = rh[0]; bh[2*g2][1] = rh[2];
                bh[2*g2+1][0] = rh[1]; bh[2*g2+1][1] = rh[3];
                bl[2*g2][0] = rl[0]; bl[2*g2][1] = rl[2];
                bl[2*g2+1][0] = rl[1]; bl[2*g2+1][1] = rl[3];
            }
            #pragma unroll
            for (int mi = 0; mi < 4; mi++)
                #pragma unroll
                for (int ni = 0; ni < 4; ni++) {
                    mma16816(acc[mi][ni], ah[mi], bh[ni]);
                    mma16816(acc[mi][ni], ah[mi], bl[ni]);
                    mma16816(acc[mi][ni], al[mi], bh[ni]);
                }
        }
        __syncthreads();
    }

    const int tr  = lane >> 2;
    const int tc2 = (lane & 3) * 2;
    #pragma unroll
    for (int mi = 0; mi < 4; mi++) {
        #pragma unroll
        for (int ni = 0; ni < 4; ni++) {
            const int col = bcol + n0w + ni * 8 + tc2;
            #pragma unroll
            for (int hf = 0; hf < 2; hf++) {
                const int row = brow + m0w + mi * 16 + tr + hf * 8;
                float v0 = acc[mi][ni][hf * 2];
                float v1 = acc[mi][ni][hf * 2 + 1];
                if (EPI == 0) {
                    *(float2*)(C + (size_t)row * N + col) = make_float2(v0, v1);
                } else if (EPI == 1) {
                    const float2 bb = *(const float2*)(bias + col);
                    const float2 rr = *(const float2*)(res + (size_t)row * N + col);
                    *(float2*)(C + (size_t)row * N + col) =
                        make_float2(v0 + bb.x + rr.x, v1 + bb.y + rr.y);
                } else {
                    const float2 bb = *(const float2*)(bias + col);
                    float g0 = gelu_exact(v0 + bb.x);
                    float g1 = gelu_exact(v1 + bb.y);
                    unsigned short h0, l0, h1, l1;
                    bf16_split(g0, h0, l0);
                    bf16_split(g1, h1, l1);
                    *(uint32_t*)(Ch + (size_t)row * N + col) =
                        (uint32_t)h0 | ((uint32_t)h1 << 16);
                    *(uint32_t*)(Cl + (size_t)row * N + col) =
                        (uint32_t)l0 | ((uint32_t)l1 << 16);
                }
            }
        }
    }
}

// ---------------- Flash attention (pairwise online softmax) -> bf16 split ----
__global__ void __launch_bounds__(128)
flash_kernel(const float* __restrict__ qkv, const int* __restrict__ mask,
             unsigned short* __restrict__ oh, unsigned short* __restrict__ ol)
{
    __shared__ __align__(16) float Ks[64][64];
    __shared__ __align__(16) float Vs[64][64];
    __shared__ unsigned char   Ms[128][68];

    const int bh = blockIdx.y;
    const int b  = bh >> 4;
    const int h  = bh & 15;
    const int q0 = blockIdx.x * 128;
    const int tid = threadIdx.x;
    const int qrow = q0 + tid;
    const float scale = 0.125f;

    float q[64];
    const float* qp = qkv + (size_t)(b * SEQ + qrow) * (3 * INNER) + h * DHEAD;
    #pragma unroll
    for (int d = 0; d < 64; d += 4) {
        float4 t = *(const float4*)(qp + d);
        q[d] = t.x * scale; q[d+1] = t.y * scale;
        q[d+2] = t.z * scale; q[d+3] = t.w * scale;
    }

    float o[64];
    #pragma unroll
    for (int d = 0; d < 64; d++) o[d] = 0.0f;
    float m = -INFINITY, l = 0.0f;

    const int* mrow = mask + ((size_t)b * SEQ + qrow) * SEQ;

    for (int kt = 0; kt < SEQ; kt += 64) {
        {
            const int r = tid >> 1;
            const int c = (tid & 1) * 32;
            const float* kp = qkv + (size_t)(b * SEQ + kt + r) * (3 * INNER)
                              + INNER + h * DHEAD + c;
            const float* vp = kp + INNER;
            #pragma unroll
            for (int j = 0; j < 32; j += 4) {
                *(float4*)&Ks[r][c + j] = *(const float4*)(kp + j);
                *(float4*)&Vs[r][c + j] = *(const float4*)(vp + j);
            }
        }
        {
            const int* mp = mrow + kt;
            #pragma unroll
            for (int j = 0; j < 64; j += 4) {
                int4 mm = *(const int4*)(mp + j);
                Ms[tid][j]     = (unsigned char)mm.x;
                Ms[tid][j + 1] = (unsigned char)mm.y;
                Ms[tid][j + 2] = (unsigned char)mm.z;
                Ms[tid][j + 3] = (unsigned char)mm.w;
            }
        }
        __syncthreads();

        // pairwise online softmax: two independent dots per iteration (ILP),
        // one shared max update + (rare) rescale per pair, fused accumulate.
        #pragma unroll 1
        for (int kk = 0; kk < 64; kk += 2) {
            float a0 = 0.f, a1 = 0.f, a2 = 0.f, a3 = 0.f;
            float c0 = 0.f, c1 = 0.f, c2 = 0.f, c3 = 0.f;
            #pragma unroll
            for (int d = 0; d < 64; d += 4) {
                float4 ka = *(const float4*)&Ks[kk][d];
                float4 kb = *(const float4*)&Ks[kk + 1][d];
                a0 += q[d]     * ka.x;
                a1 += q[d + 1] * ka.y;
                a2 += q[d + 2] * ka.z;
                a3 += q[d + 3] * ka.w;
                c0 += q[d]     * kb.x;
                c1 += q[d + 1] * kb.y;
                c2 += q[d + 2] * kb.z;
                c3 += q[d + 3] * kb.w;
            }
            float sA = (a0 + a1) + (a2 + a3);
            float sB = (c0 + c1) + (c2 + c3);
            if (Ms[tid][kk] == 0)     sA = -1e9f;
            if (Ms[tid][kk + 1] == 0) sB = -1e9f;

            const float mnew = fmaxf(m, fmaxf(sA, sB));
            if (mnew > m) {
                const float cr = __expf(m - mnew);   // expf(-inf)=0 handles init
                l *= cr;
                #pragma unroll
                for (int d = 0; d < 64; d++) o[d] *= cr;
                m = mnew;
            }
            const float pA = __expf(sA - m);
            const float pB = __expf(sB - m);
            l += pA + pB;
            #pragma unroll
            for (int d = 0; d < 64; d += 4) {
                float4 va = *(const float4*)&Vs[kk][d];
                float4 vb = *(const float4*)&Vs[kk + 1][d];
                o[d]     += pA * va.x + pB * vb.x;
                o[d + 1] += pA * va.y + pB * vb.y;
                o[d + 2] += pA * va.z + pB * vb.z;
                o[d + 3] += pA * va.w + pB * vb.w;
            }
        }
        __syncthreads();
    }

    const float inv = 1.0f / l;
    unsigned short* hp = oh + (size_t)(b * SEQ + qrow) * INNER + h * DHEAD;
    unsigned short* lp = ol + (size_t)(b * SEQ + qrow) * INNER + h * DHEAD;
    #pragma unroll
    for (int d0 = 0; d0 < 64; d0 += 8) {
        uint32_t hw[4], lw[4];
        #pragma unroll
        for (int j = 0; j < 4; j++) {
            float v0 = o[d0 + 2*j]     * inv;
            float v1 = o[d0 + 2*j + 1] * inv;
            unsigned short h0, l0, h1, l1;
            bf16_split(v0, h0, l0);
            bf16_split(v1, h1, l1);
            hw[j] = (uint32_t)h0 | ((uint32_t)h1 << 16);
            lw[j] = (uint32_t)l0 | ((uint32_t)l1 << 16);
        }
        *(uint4*)(hp + d0) = make_uint4(hw[0], hw[1], hw[2], hw[3]);
        *(uint4*)(lp + d0) = make_uint4(lw[0], lw[1], lw[2], lw[3]);
    }
}

// ---------------- host orchestration ----------------------------------------
extern "C" void kernel_launch(void* const* d_in, const int* in_sizes, int n_in,
                              void* d_out, int out_size)
{
    (void)in_sizes; (void)n_in; (void)out_size;
    const float* x_in  = (const float*)d_in[0];
    const int*   mask  = (const int*)  d_in[1];
    const float* ln1_g = (const float*)d_in[2];
    const float* ln1_b = (const float*)d_in[3];
    const float* qkv_w = (const float*)d_in[4];
    const float* out_w = (const float*)d_in[5];
    const float* out_b = (const float*)d_in[6];
    const float* ln2_g = (const float*)d_in[7];
    const float* ln2_b = (const float*)d_in[8];
    const float* ff1_w = (const float*)d_in[9];
    const float* ff1_b = (const float*)d_in[10];
    const float* ff2_w = (const float*)d_in[11];
    const float* ff2_b = (const float*)d_in[12];

    cudaFuncSetAttribute(mma_gemm<0>, cudaFuncAttributeMaxDynamicSharedMemorySize, GSMEM_B);
    cudaFuncSetAttribute(mma_gemm<1>, cudaFuncAttributeMaxDynamicSharedMemorySize, GSMEM_B);
    cudaFuncSetAttribute(mma_gemm<2>, cudaFuncAttributeMaxDynamicSharedMemorySize, GSMEM_B);

    float *p_qkv, *p_x;
    __nv_bfloat16 *p_ah, *p_al, *p_fh, *p_fl;
    __nv_bfloat16 *pwqh, *pwql, *pwoh, *pwol, *pw1h, *pw1l, *pw2h, *pw2l;
    cudaGetSymbolAddress((void**)&p_qkv, g_qkv);
    cudaGetSymbolAddress((void**)&p_x,   g_x);
    cudaGetSymbolAddress((void**)&p_ah,  g_ah);
    cudaGetSymbolAddress((void**)&p_al,  g_al);
    cudaGetSymbolAddress((void**)&p_fh,  g_fh);
    cudaGetSymbolAddress((void**)&p_fl,  g_fl);
    cudaGetSymbolAddress((void**)&pwqh,  w_qkv_h);
    cudaGetSymbolAddress((void**)&pwql,  w_qkv_l);
    cudaGetSymbolAddress((void**)&pwoh,  w_out_h);
    cudaGetSymbolAddress((void**)&pwol,  w_out_l);
    cudaGetSymbolAddress((void**)&pw1h,  w_ff1_h);
    cudaGetSymbolAddress((void**)&pw1l,  w_ff1_l);
    cudaGetSymbolAddress((void**)&pw2h,  w_ff2_h);
    cudaGetSymbolAddress((void**)&pw2l,  w_ff2_l);

    // ---- per-call weight transpose + split ----
    const dim3 cb(32, 8);
    for (int l = 0; l < DEPTH; l++) {
        wconv_kernel<<<dim3(3*INNER/32, DIMV/32), cb>>>(
            qkv_w + (size_t)l * DIMV * 3*INNER,
            pwqh + (size_t)l * 3*INNER * DIMV, pwql + (size_t)l * 3*INNER * DIMV,
            DIMV, 3*INNER);
        wconv_kernel<<<dim3(DIMV/32, INNER/32), cb>>>(
            out_w + (size_t)l * INNER * DIMV,
            pwoh + (size_t)l * DIMV * INNER, pwol + (size_t)l * DIMV * INNER,
            INNER, DIMV);
        wconv_kernel<<<dim3(MLPV/32, DIMV/32), cb>>>(
            ff1_w + (size_t)l * DIMV * MLPV,
            pw1h + (size_t)l * MLPV * DIMV, pw1l + (size_t)l * MLPV * DIMV,
            DIMV, MLPV);
        wconv_kernel<<<dim3(DIMV/32, MLPV/32), cb>>>(
            ff2_w + (size_t)l * MLPV * DIMV,
            pw2h + (size_t)l * DIMV * MLPV, pw2l + (size_t)l * DIMV * MLPV,
            MLPV, DIMV);
    }

    for (int l = 0; l < DEPTH; l++) {
        const float* xsrc = (l == 0) ? x_in : p_x;

        // h = LN1(x) -> bf16 split
        ln_kernel<<<ROWS, 256>>>(xsrc, ln1_g + l * DIMV, ln1_b + l * DIMV,
                                 (unsigned short*)p_ah, (unsigned short*)p_al);

        // qkv = h @ qkv_w[l]  (fp32 out for attention)
        mma_gemm<0><<<dim3(3*INNER/128, ROWS/128), 256, GSMEM_B>>>(
            p_ah, p_al,
            pwqh + (size_t)l * 3*INNER * DIMV, pwql + (size_t)l * 3*INNER * DIMV,
            p_qkv, nullptr, nullptr, nullptr, nullptr, 3*INNER, DIMV);

        // o = attention(q,k,v,mask) -> bf16 split
        flash_kernel<<<dim3(SEQ/128, BATCH*HEADS), 128>>>(
            p_qkv, mask, (unsigned short*)p_ah, (unsigned short*)p_al);

        // x = o @ out_w[l] + out_b[l] + x
        mma_gemm<1><<<dim3(DIMV/128, ROWS/128), 256, GSMEM_B>>>(
            p_ah, p_al,
            pwoh + (size_t)l * DIMV * INNER, pwol + (size_t)l * DIMV * INNER,
            p_x, out_b + l * DIMV, xsrc, nullptr, nullptr, DIMV, INNER);

        // h = LN2(x) -> bf16 split
        ln_kernel<<<ROWS, 256>>>(p_x, ln2_g + l * DIMV, ln2_b + l * DIMV,
                                 (unsigned short*)p_ah, (unsigned short*)p_al);

        // ffh = gelu(h @ ff1_w[l] + ff1_b[l]) -> bf16 split
        mma_gemm<2><<<dim3(MLPV/128, ROWS/128), 256, GSMEM_B>>>(
            p_ah, p_al,
            pw1h + (size_t)l * MLPV * DIMV, pw1l + (size_t)l * MLPV * DIMV,
            nullptr, ff1_b + l * MLPV, nullptr,
            (unsigned short*)p_fh, (unsigned short*)p_fl, MLPV, DIMV);

        // x = ffh @ ff2_w[l] + ff2_b[l] + x   (last layer writes d_out)
        float* xdst = (l == DEPTH - 1) ? (float*)d_out : p_x;
        mma_gemm<1><<<dim3(DIMV/128, ROWS/128), 256, GSMEM_B>>>(
            p_fh, p_fl,
            pw2h + (size_t)l * DIMV * MLPV, pw2l + (size_t)l * DIMV * MLPV,
            xdst, ff2_b + l * DIMV, p_x, nullptr, nullptr, DIMV, MLPV);
    }
}

// round 14
// speedup vs baseline: 1.1131x; 1.0421x over previous
#include <cuda_runtime.h>
#include <cuda_bf16.h>
#include <math.h>
#include <stdint.h>

#define DIMV   1024
#define DEPTH  4
#define HEADS  16
#define DHEAD  64
#define INNER  1024
#define MLPV   4096
#define BATCH  2
#define SEQ    1024
#define ROWS   (BATCH*SEQ)

typedef unsigned long long ull;

// ---------------- scratch (no allocations allowed; __device__ globals) -------
__device__ float g_qkv[ROWS * 3 * INNER];            // qkv projection (fp32, 24MB)
__device__ float g_x  [ROWS * DIMV];                 // residual stream (8MB)
__device__ __nv_bfloat16 g_ah[ROWS * DIMV];          // activation split hi
__device__ __nv_bfloat16 g_al[ROWS * DIMV];          // activation split lo
__device__ __nv_bfloat16 g_fh[ROWS * MLPV];          // ff hidden split hi
__device__ __nv_bfloat16 g_fl[ROWS * MLPV];          // ff hidden split lo
// transposed + split weights  [N][K] bf16
__device__ __nv_bfloat16 w_qkv_h[DEPTH * 3*INNER * DIMV];
__device__ __nv_bfloat16 w_qkv_l[DEPTH * 3*INNER * DIMV];
__device__ __nv_bfloat16 w_out_h[DEPTH * DIMV * INNER];
__device__ __nv_bfloat16 w_out_l[DEPTH * DIMV * INNER];
__device__ __nv_bfloat16 w_ff1_h[DEPTH * MLPV * DIMV];
__device__ __nv_bfloat16 w_ff1_l[DEPTH * MLPV * DIMV];
__device__ __nv_bfloat16 w_ff2_h[DEPTH * DIMV * MLPV];
__device__ __nv_bfloat16 w_ff2_l[DEPTH * DIMV * MLPV];

// ---------------- small helpers ---------------------------------------------
__device__ __forceinline__ void bf16_split(float v, unsigned short& h, unsigned short& l)
{
    __nv_bfloat16 hb = __float2bfloat16(v);
    __nv_bfloat16 lb = __float2bfloat16(v - __bfloat162float(hb));
    h = __bfloat16_as_ushort(hb);
    l = __bfloat16_as_ushort(lb);
}

__device__ __forceinline__ float gelu_exact(float x)
{
    return 0.5f * x * (1.0f + erff(x * 0.70710678118654752f));
}

__device__ __forceinline__ uint32_t smem_u32(const void* p)
{
    uint32_t r;
    asm("{ .reg .u64 t; cvta.to.shared.u64 t, %1; cvt.u32.u64 %0, t; }"
        : "=r"(r) : "l"(p));
    return r;
}

// ---------------- packed f32x2 (Blackwell FFMA2 via explicit PTX) -----------
__device__ __forceinline__ ull pack2(float a, float b)
{
    ull r; asm("mov.b64 %0, {%1, %2};" : "=l"(r) : "f"(a), "f"(b)); return r;
}
__device__ __forceinline__ void unpack2(ull v, float& a, float& b)
{
    asm("mov.b64 {%0, %1}, %2;" : "=f"(a), "=f"(b) : "l"(v));
}
#define FMA2(d, a, b, c) \
    asm("fma.rn.f32x2 %0, %1, %2, %3;" : "=l"(d) : "l"(a), "l"(b), "l"(c))
#define MUL2(d, a, b) \
    asm("mul.rn.f32x2 %0, %1, %2;" : "=l"(d) : "l"(a), "l"(b))

// ---------------- mma.sync / ldmatrix / cp.async wrappers (sm_80+ PTX) -------
__device__ __forceinline__ void ldsm4(uint32_t* r, uint32_t addr)
{
    asm volatile("ldmatrix.sync.aligned.m8n8.x4.shared.b16 {%0,%1,%2,%3}, [%4];"
        : "=r"(r[0]), "=r"(r[1]), "=r"(r[2]), "=r"(r[3]) : "r"(addr));
}

__device__ __forceinline__ void mma16816(float* d, const uint32_t* a, const uint32_t* b)
{
    asm volatile(
        "mma.sync.aligned.m16n8k16.row.col.f32.bf16.bf16.f32 "
        "{%0,%1,%2,%3}, {%4,%5,%6,%7}, {%8,%9}, {%0,%1,%2,%3};"
        : "+f"(d[0]), "+f"(d[1]), "+f"(d[2]), "+f"(d[3])
        : "r"(a[0]), "r"(a[1]), "r"(a[2]), "r"(a[3]), "r"(b[0]), "r"(b[1]));
}

#define CP_ASYNC16(dst, src) \
    asm volatile("cp.async.cg.shared.global [%0], [%1], 16;" :: "r"(dst), "l"(src))
#define CP_COMMIT() asm volatile("cp.async.commit_group;" ::: "memory")
#define CP_WAIT1()  asm volatile("cp.async.wait_group 1;" ::: "memory")
#define CP_WAIT0()  asm volatile("cp.async.wait_group 0;" ::: "memory")

// ---------------- LayerNorm -> bf16 split ------------------------------------
__global__ void ln_kernel(const float* __restrict__ x,
                          const float* __restrict__ g,
                          const float* __restrict__ b,
                          unsigned short* __restrict__ oh,
                          unsigned short* __restrict__ ol)
{
    __shared__ float red[8];
    __shared__ float sh_mu, sh_rs;
    const int row = blockIdx.x;
    const int tid = threadIdx.x;          // 256 threads, 4 elems each
    float4 v = ((const float4*)(x + (size_t)row * DIMV))[tid];

    float s = (v.x + v.y) + (v.z + v.w);
    #pragma unroll
    for (int o = 16; o; o >>= 1) s += __shfl_xor_sync(0xffffffffu, s, o);
    if ((tid & 31) == 0) red[tid >> 5] = s;
    __syncthreads();
    if (tid == 0) {
        float t = red[0];
        #pragma unroll
        for (int i = 1; i < 8; i++) t += red[i];
        sh_mu = t * (1.0f / DIMV);
    }
    __syncthreads();
    const float mu = sh_mu;
    float d0 = v.x - mu, d1 = v.y - mu, d2 = v.z - mu, d3 = v.w - mu;
    s = d0*d0 + d1*d1 + d2*d2 + d3*d3;
    #pragma unroll
    for (int o = 16; o; o >>= 1) s += __shfl_xor_sync(0xffffffffu, s, o);
    if ((tid & 31) == 0) red[tid >> 5] = s;
    __syncthreads();
    if (tid == 0) {
        float t = red[0];
        #pragma unroll
        for (int i = 1; i < 8; i++) t += red[i];
        sh_rs = rsqrtf(t * (1.0f / DIMV) + 1e-5f);
    }
    __syncthreads();
    const float rs = sh_rs;
    float4 gg = ((const float4*)g)[tid];
    float4 bb = ((const float4*)b)[tid];
    float r0 = d0 * rs * gg.x + bb.x;
    float r1 = d1 * rs * gg.y + bb.y;
    float r2 = d2 * rs * gg.z + bb.z;
    float r3 = d3 * rs * gg.w + bb.w;
    unsigned short h0,h1,h2,h3,l0,l1,l2,l3;
    bf16_split(r0,h0,l0); bf16_split(r1,h1,l1);
    bf16_split(r2,h2,l2); bf16_split(r3,h3,l3);
    uint2 H, L;
    H.x = (uint32_t)h0 | ((uint32_t)h1 << 16);
    H.y = (uint32_t)h2 | ((uint32_t)h3 << 16);
    L.x = (uint32_t)l0 | ((uint32_t)l1 << 16);
    L.y = (uint32_t)l2 | ((uint32_t)l3 << 16);
    ((uint2*)(oh + (size_t)row * DIMV))[tid] = H;
    ((uint2*)(ol + (size_t)row * DIMV))[tid] = L;
}

// ---------------- weight transpose + bf16 split ------------------------------
// W [K][N] fp32 row-major -> Wh/Wl [N][K] bf16
__global__ void wconv_kernel(const float* __restrict__ W,
                             __nv_bfloat16* __restrict__ Wh,
                             __nv_bfloat16* __restrict__ Wl, int K, int N)
{
    __shared__ float t[32][33];
    const int tx = threadIdx.x, ty = threadIdx.y;   // block (32, 8)
    const int k0 = blockIdx.y * 32, n0 = blockIdx.x * 32;
    #pragma unroll
    for (int j = 0; j < 4; j++)
        t[ty + j*8][tx] = W[(size_t)(k0 + ty + j*8) * N + n0 + tx];
    __syncthreads();
    #pragma unroll
    for (int j = 0; j < 4; j++) {
        float v = t[tx][ty + j*8];
        __nv_bfloat16 hb = __float2bfloat16(v);
        __nv_bfloat16 lb = __float2bfloat16(v - __bfloat162float(hb));
        size_t o = (size_t)(n0 + ty + j*8) * K + k0 + tx;
        Wh[o] = hb; Wl[o] = lb;
    }
}

// ---------------- mma.sync GEMM (TN=128): proven R12 kernel ------------------
// 3-term bf16 split: Ah*Bh + Ah*Bl + Al*Bh.
// CTA tile 128x128, 8 warps (warp tile 64x32), K-chunk 32, cp.async 2 stages.
// EPI: 0 = plain fp32, 1 = +bias +residual fp32, 2 = +bias +GELU -> bf16 hi/lo
#define PITCH    40                    // bf16 elems per smem row (80B, LDSM conflict-free)
#define TILE_B   (128 * PITCH * 2)     // 10240 B per tile
#define STAGE_B  (4 * TILE_B)          // Ah, Al, Bh, Bl
#define GSMEM_B  (2 * STAGE_B)         // 81920 B

template <int EPI>
__global__ void __launch_bounds__(256, 2)
mma_gemm(const __nv_bfloat16* __restrict__ Ah, const __nv_bfloat16* __restrict__ Al,
         const __nv_bfloat16* __restrict__ Bh, const __nv_bfloat16* __restrict__ Bl,
         float* __restrict__ C, const float* __restrict__ bias,
         const float* __restrict__ res,
         unsigned short* __restrict__ Ch, unsigned short* __restrict__ Cl,
         int N, int K)
{
    extern __shared__ __align__(128) char smem[];
    const uint32_t sb = smem_u32(smem);
    const int tid  = threadIdx.x;
    const int wid  = tid >> 5, lane = tid & 31;
    const int brow = blockIdx.y * 128, bcol = blockIdx.x * 128;

    const int prow = tid >> 1;
    const int pp   = (tid & 1) * 2;
    const size_t kstride = (size_t)K * 2;

    const char* ga[4];
    ga[0] = (const char*)Ah + (size_t)(brow + prow) * kstride + pp * 16;
    ga[1] = (const char*)Al + (size_t)(brow + prow) * kstride + pp * 16;
    ga[2] = (const char*)Bh + (size_t)(bcol + prow) * kstride + pp * 16;
    ga[3] = (const char*)Bl + (size_t)(bcol + prow) * kstride + pp * 16;
    const uint32_t sdst = sb + (uint32_t)prow * (PITCH * 2) + (uint32_t)pp * 16;

    auto load_chunk = [&](int s, int c) {
        const size_t ko = (size_t)c * 64;
        const uint32_t stg = sdst + s * STAGE_B;
        #pragma unroll
        for (int t = 0; t < 4; t++) {
            const char* g = ga[t] + ko;
            CP_ASYNC16(stg + t * TILE_B,      g);
            CP_ASYNC16(stg + t * TILE_B + 16, g + 16);
        }
    };

    const int m0w = (wid & 1) * 64;
    const int n0w = (wid >> 1) * 32;
    const int lr  = lane & 15;
    const int lc  = (lane >> 4) * 16;

    float acc[4][4][4];
    #pragma unroll
    for (int i = 0; i < 4; i++)
        #pragma unroll
        for (int j = 0; j < 4; j++)
            #pragma unroll
            for (int q = 0; q < 4; q++) acc[i][j][q] = 0.0f;

    const int NC = K >> 5;
    load_chunk(0, 0);
    CP_COMMIT();

    for (int c = 0; c < NC; c++) {
        const int s = c & 1;
        if (c + 1 < NC) { load_chunk(s ^ 1, c + 1); CP_COMMIT(); CP_WAIT1(); }
        else            { CP_WAIT0(); }
        __syncthreads();

        const uint32_t stg = sb + s * STAGE_B;
        const uint32_t sAh = stg;
        const uint32_t sAl = stg + TILE_B;
        const uint32_t sBh = stg + 2 * TILE_B;
        const uint32_t sBl = stg + 3 * TILE_B;

        #pragma unroll
        for (int kb = 0; kb < 2; kb++) {
            const uint32_t kofs = kb * 32 + lc;
            uint32_t ah[4][4], al[4][4], bh[4][2], bl[4][2];
            #pragma unroll
            for (int mi = 0; mi < 4; mi++) {
                const uint32_t ro = (uint32_t)(m0w + mi * 16 + lr) * (PITCH * 2) + kofs;
                ldsm4(ah[mi], sAh + ro);
                ldsm4(al[mi], sAl + ro);
            }
            #pragma unroll
            for (int g2 = 0; g2 < 2; g2++) {
                const uint32_t ro = (uint32_t)(n0w + g2 * 16 + lr) * (PITCH * 2) + kofs;
                uint32_t rh[4], rl[4];
                ldsm4(rh, sBh + ro);
                ldsm4(rl, sBl + ro);
                bh[2*g2][0] = rh[0]; bh[2*g2][1] = rh[2];
                bh[2*g2+1][0] = rh[1]; bh[2*g2+1][1] = rh[3];
                bl[2*g2][0] = rl[0]; bl[2*g2][1] = rl[2];
                bl[2*g2+1][0] = rl[1]; bl[2*g2+1][1] = rl[3];
            }
            #pragma unroll
            for (int mi = 0; mi < 4; mi++)
                #pragma unroll
                for (int ni = 0; ni < 4; ni++) {
                    mma16816(acc[mi][ni], ah[mi], bh[ni]);
                    mma16816(acc[mi][ni], ah[mi], bl[ni]);
                    mma16816(acc[mi][ni], al[mi], bh[ni]);
                }
        }
        __syncthreads();
    }

    const int tr  = lane >> 2;
    const int tc2 = (lane & 3) * 2;
    #pragma unroll
    for (int mi = 0; mi < 4; mi++) {
        #pragma unroll
        for (int ni = 0; ni < 4; ni++) {
            const int col = bcol + n0w + ni * 8 + tc2;
            #pragma unroll
            for (int hf = 0; hf < 2; hf++) {
                const int row = brow + m0w + mi * 16 + tr + hf * 8;
                float v0 = acc[mi][ni][hf * 2];
                float v1 = acc[mi][ni][hf * 2 + 1];
                if (EPI == 0) {
                    *(float2*)(C + (size_t)row * N + col) = make_float2(v0, v1);
                } else if (EPI == 1) {
                    const float2 bb = *(const float2*)(bias + col);
                    const float2 rr = *(const float2*)(res + (size_t)row * N + col);
                    *(float2*)(C + (size_t)row * N + col) =
                        make_float2(v0 + bb.x + rr.x, v1 + bb.y + rr.y);
                } else {
                    const float2 bb = *(const float2*)(bias + col);
                    float g0 = gelu_exact(v0 + bb.x);
                    float g1 = gelu_exact(v1 + bb.y);
                    unsigned short h0, l0, h1, l1;
                    bf16_split(g0, h0, l0);
                    bf16_split(g1, h1, l1);
                    *(uint32_t*)(Ch + (size_t)row * N + col) =
                        (uint32_t)h0 | ((uint32_t)h1 << 16);
                    *(uint32_t*)(Cl + (size_t)row * N + col) =
                        (uint32_t)l0 | ((uint32_t)l1 << 16);
                }
            }
        }
    }
}

// ---------------- Flash attention (pairwise online softmax, f32x2) ----------
__global__ void __launch_bounds__(128)
flash_kernel(const float* __restrict__ qkv, const int* __restrict__ mask,
             unsigned short* __restrict__ oh, unsigned short* __restrict__ ol)
{
    __shared__ __align__(16) float Ks[64][64];
    __shared__ __align__(16) float Vs[64][64];
    __shared__ unsigned char   Ms[128][68];

    const int bh = blockIdx.y;
    const int b  = bh >> 4;
    const int h  = bh & 15;
    const int q0 = blockIdx.x * 128;
    const int tid = threadIdx.x;
    const int qrow = q0 + tid;
    const float scale = 0.125f;

    // q packed as 32 x f32x2
    ull q2[32];
    const float* qp = qkv + (size_t)(b * SEQ + qrow) * (3 * INNER) + h * DHEAD;
    #pragma unroll
    for (int d = 0; d < 64; d += 4) {
        float4 t = *(const float4*)(qp + d);
        q2[d/2]     = pack2(t.x * scale, t.y * scale);
        q2[d/2 + 1] = pack2(t.z * scale, t.w * scale);
    }

    // o accumulator packed as 32 x f32x2
    ull o2[32];
    #pragma unroll
    for (int j = 0; j < 32; j++) o2[j] = 0ull;
    float m = -INFINITY, l = 0.0f;

    const int* mrow = mask + ((size_t)b * SEQ + qrow) * SEQ;

    for (int kt = 0; kt < SEQ; kt += 64) {
        {
            const int r = tid >> 1;
            const int c = (tid & 1) * 32;
            const float* kp = qkv + (size_t)(b * SEQ + kt + r) * (3 * INNER)
                              + INNER + h * DHEAD + c;
            const float* vp = kp + INNER;
            #pragma unroll
            for (int j = 0; j < 32; j += 4) {
                *(float4*)&Ks[r][c + j] = *(const float4*)(kp + j);
                *(float4*)&Vs[r][c + j] = *(const float4*)(vp + j);
            }
        }
        {
            const int* mp = mrow + kt;
            #pragma unroll
            for (int j = 0; j < 64; j += 4) {
                int4 mm = *(const int4*)(mp + j);
                Ms[tid][j]     = (unsigned char)mm.x;
                Ms[tid][j + 1] = (unsigned char)mm.y;
                Ms[tid][j + 2] = (unsigned char)mm.z;
                Ms[tid][j + 3] = (unsigned char)mm.w;
            }
        }
        __syncthreads();

        #pragma unroll 1
        for (int kk = 0; kk < 64; kk += 2) {
            // --- packed dots for both keys (4 independent FMA2 chains) ---
            ull sAa = 0ull, sAb = 0ull, sBa = 0ull, sBb = 0ull;
            const ulonglong2* ka = (const ulonglong2*)&Ks[kk][0];
            const ulonglong2* kb = (const ulonglong2*)&Ks[kk + 1][0];
            #pragma unroll
            for (int j = 0; j < 16; j++) {
                ulonglong2 kA = ka[j];
                ulonglong2 kB = kb[j];
                FMA2(sAa, q2[2*j],     kA.x, sAa);
                FMA2(sAb, q2[2*j + 1], kA.y, sAb);
                FMA2(sBa, q2[2*j],     kB.x, sBa);
                FMA2(sBb, q2[2*j + 1], kB.y, sBb);
            }
            float x0, x1, y0, y1;
            unpack2(sAa, x0, x1); unpack2(sAb, y0, y1);
            float sA = (x0 + x1) + (y0 + y1);
            unpack2(sBa, x0, x1); unpack2(sBb, y0, y1);
            float sB = (x0 + x1) + (y0 + y1);

            if (Ms[tid][kk] == 0)     sA = -1e9f;
            if (Ms[tid][kk + 1] == 0) sB = -1e9f;

            const float mnew = fmaxf(m, fmaxf(sA, sB));
            if (mnew > m) {
                const float cr = __expf(m - mnew);   // expf(-inf)=0 handles init
                l *= cr;
                const ull cr2 = pack2(cr, cr);
                #pragma unroll
                for (int j = 0; j < 32; j++) MUL2(o2[j], o2[j], cr2);
                m = mnew;
            }
            const float pA = __expf(sA - m);
            const float pB = __expf(sB - m);
            l += pA + pB;

            const ull pA2 = pack2(pA, pA);
            const ull pB2 = pack2(pB, pB);
            const ulonglong2* va = (const ulonglong2*)&Vs[kk][0];
            const ulonglong2* vb = (const ulonglong2*)&Vs[kk + 1][0];
            #pragma unroll
            for (int j = 0; j < 16; j++) {
                ulonglong2 vA = va[j];
                ulonglong2 vB = vb[j];
                ull t0, t1;
                FMA2(t0, pA2, vA.x, o2[2*j]);
                FMA2(o2[2*j], pB2, vB.x, t0);
                FMA2(t1, pA2, vA.y, o2[2*j + 1]);
                FMA2(o2[2*j + 1], pB2, vB.y, t1);
            }
        }
        __syncthreads();
    }

    const float inv = 1.0f / l;
    const ull inv2 = pack2(inv, inv);
    unsigned short* hp = oh + (size_t)(b * SEQ + qrow) * INNER + h * DHEAD;
    unsigned short* lp = ol + (size_t)(b * SEQ + qrow) * INNER + h * DHEAD;
    #pragma unroll
    for (int d0 = 0; d0 < 64; d0 += 8) {
        uint32_t hw[4], lw[4];
        #pragma unroll
        for (int j = 0; j < 4; j++) {
            ull t;
            MUL2(t, o2[(d0 + 2*j) / 2], inv2);
            float v0, v1;
            unpack2(t, v0, v1);
            unsigned short h0, l0, h1, l1;
            bf16_split(v0, h0, l0);
            bf16_split(v1, h1, l1);
            hw[j] = (uint32_t)h0 | ((uint32_t)h1 << 16);
            lw[j] = (uint32_t)l0 | ((uint32_t)l1 << 16);
        }
        *(uint4*)(hp + d0) = make_uint4(hw[0], hw[1], hw[2], hw[3]);
        *(uint4*)(lp + d0) = make_uint4(lw[0], lw[1], lw[2], lw[3]);
    }
}

// ---------------- host orchestration ----------------------------------------
extern "C" void kernel_launch(void* const* d_in, const int* in_sizes, int n_in,
                              void* d_out, int out_size)
{
    (void)in_sizes; (void)n_in; (void)out_size;
    const float* x_in  = (const float*)d_in[0];
    const int*   mask  = (const int*)  d_in[1];
    const float* ln1_g = (const float*)d_in[2];
    const float* ln1_b = (const float*)d_in[3];
    const float* qkv_w = (const float*)d_in[4];
    const float* out_w = (const float*)d_in[5];
    const float* out_b = (const float*)d_in[6];
    const float* ln2_g = (const float*)d_in[7];
    const float* ln2_b = (const float*)d_in[8];
    const float* ff1_w = (const float*)d_in[9];
    const float* ff1_b = (const float*)d_in[10];
    const float* ff2_w = (const float*)d_in[11];
    const float* ff2_b = (const float*)d_in[12];

    cudaFuncSetAttribute(mma_gemm<0>, cudaFuncAttributeMaxDynamicSharedMemorySize, GSMEM_B);
    cudaFuncSetAttribute(mma_gemm<1>, cudaFuncAttributeMaxDynamicSharedMemorySize, GSMEM_B);
    cudaFuncSetAttribute(mma_gemm<2>, cudaFuncAttributeMaxDynamicSharedMemorySize, GSMEM_B);

    float *p_qkv, *p_x;
    __nv_bfloat16 *p_ah, *p_al, *p_fh, *p_fl;
    __nv_bfloat16 *pwqh, *pwql, *pwoh, *pwol, *pw1h, *pw1l, *pw2h, *pw2l;
    cudaGetSymbolAddress((void**)&p_qkv, g_qkv);
    cudaGetSymbolAddress((void**)&p_x,   g_x);
    cudaGetSymbolAddress((void**)&p_ah,  g_ah);
    cudaGetSymbolAddress((void**)&p_al,  g_al);
    cudaGetSymbolAddress((void**)&p_fh,  g_fh);
    cudaGetSymbolAddress((void**)&p_fl,  g_fl);
    cudaGetSymbolAddress((void**)&pwqh,  w_qkv_h);
    cudaGetSymbolAddress((void**)&pwql,  w_qkv_l);
    cudaGetSymbolAddress((void**)&pwoh,  w_out_h);
    cudaGetSymbolAddress((void**)&pwol,  w_out_l);
    cudaGetSymbolAddress((void**)&pw1h,  w_ff1_h);
    cudaGetSymbolAddress((void**)&pw1l,  w_ff1_l);
    cudaGetSymbolAddress((void**)&pw2h,  w_ff2_h);
    cudaGetSymbolAddress((void**)&pw2l,  w_ff2_l);

    // ---- per-call weight transpose + split ----
    const dim3 cb(32, 8);
    for (int l = 0; l < DEPTH; l++) {
        wconv_kernel<<<dim3(3*INNER/32, DIMV/32), cb>>>(
            qkv_w + (size_t)l * DIMV * 3*INNER,
            pwqh + (size_t)l * 3*INNER * DIMV, pwql + (size_t)l * 3*INNER * DIMV,
            DIMV, 3*INNER);
        wconv_kernel<<<dim3(DIMV/32, INNER/32), cb>>>(
            out_w + (size_t)l * INNER * DIMV,
            pwoh + (size_t)l * DIMV * INNER, pwol + (size_t)l * DIMV * INNER,
            INNER, DIMV);
        wconv_kernel<<<dim3(MLPV/32, DIMV/32), cb>>>(
            ff1_w + (size_t)l * DIMV * MLPV,
            pw1h + (size_t)l * MLPV * DIMV, pw1l + (size_t)l * MLPV * DIMV,
            DIMV, MLPV);
        wconv_kernel<<<dim3(DIMV/32, MLPV/32), cb>>>(
            ff2_w + (size_t)l * MLPV * DIMV,
            pw2h + (size_t)l * DIMV * MLPV, pw2l + (size_t)l * DIMV * MLPV,
            MLPV, DIMV);
    }

    for (int l = 0; l < DEPTH; l++) {
        const float* xsrc = (l == 0) ? x_in : p_x;

        // h = LN1(x) -> bf16 split
        ln_kernel<<<ROWS, 256>>>(xsrc, ln1_g + l * DIMV, ln1_b + l * DIMV,
                                 (unsigned short*)p_ah, (unsigned short*)p_al);

        // qkv = h @ qkv_w[l]  (fp32 out for attention)
        mma_gemm<0><<<dim3(3*INNER/128, ROWS/128), 256, GSMEM_B>>>(
            p_ah, p_al,
            pwqh + (size_t)l * 3*INNER * DIMV, pwql + (size_t)l * 3*INNER * DIMV,
            p_qkv, nullptr, nullptr, nullptr, nullptr, 3*INNER, DIMV);

        // o = attention(q,k,v,mask) -> bf16 split
        flash_kernel<<<dim3(SEQ/128, BATCH*HEADS), 128>>>(
            p_qkv, mask, (unsigned short*)p_ah, (unsigned short*)p_al);

        // x = o @ out_w[l] + out_b[l] + x
        mma_gemm<1><<<dim3(DIMV/128, ROWS/128), 256, GSMEM_B>>>(
            p_ah, p_al,
            pwoh + (size_t)l * DIMV * INNER, pwol + (size_t)l * DIMV * INNER,
            p_x, out_b + l * DIMV, xsrc, nullptr, nullptr, DIMV, INNER);

        // h = LN2(x) -> bf16 split
        ln_kernel<<<ROWS, 256>>>(p_x, ln2_g + l * DIMV, ln2_b + l * DIMV,
                                 (unsigned short*)p_ah, (unsigned short*)p_al);

        // ffh = gelu(h @ ff1_w[l] + ff1_b[l]) -> bf16 split
        mma_gemm<2><<<dim3(MLPV/128, ROWS/128), 256, GSMEM_B>>>(
            p_ah, p_al,
            pw1h + (size_t)l * MLPV * DIMV, pw1l + (size_t)l * MLPV * DIMV,
            nullptr, ff1_b + l * MLPV, nullptr,
            (unsigned short*)p_fh, (unsigned short*)p_fl, MLPV, DIMV);

        // x = ffh @ ff2_w[l] + ff2_b[l] + x   (last layer writes d_out)
        float* xdst = (l == DEPTH - 1) ? (float*)d_out : p_x;
        mma_gemm<1><<<dim3(DIMV/128, ROWS/128), 256, GSMEM_B>>>(
            p_fh, p_fl,
            pw2h + (size_t)l * DIMV * MLPV, pw2l + (size_t)l * DIMV * MLPV,
            xdst, ff2_b + l * DIMV, p_x, nullptr, nullptr, DIMV, MLPV);
    }
}